// round 2
// baseline (speedup 1.0000x reference)
#include <cuda_runtime.h>
#include <math.h>
#include <stdint.h>

#define BB 128
#define HH 512
#define SS 2048

// Scratch (device globals: no allocations allowed)
__device__ float g_u_part[4][BB][SS];   // partial u per h-tile
__device__ float g_attn[BB][SS];
__device__ float g_context[BB][HH];
__device__ float g_h1[BB][HH];
__device__ float g_mlp_out[BB][HH];

__device__ __forceinline__ unsigned int f2tf32(float x) {
    unsigned int r;
    asm("cvt.rna.tf32.f32 %0, %1;" : "=r"(r) : "f"(x));
    return r;
}

// ---------------------------------------------------------------------------
// Kernel 1: u_part[ht][b][s] = sum_{h in tile} v_att[h] * tanh( (W @ ah_b)[h,s] )
// tf32 mma.sync tiled GEMM, tile 128(M=h) x 128(N=s), K chunk 32.
// grid: (S/128, H/128, B) = (16, 4, 128), 256 threads (8 warps, 2x4).
// ---------------------------------------------------------------------------
#define AS_STRIDE 36   // 4*m + t distinct banks for A frag loads
#define BS_STRIDE 136  // 8*t + g distinct banks for B frag loads

__global__ __launch_bounds__(256) void scores_u_kernel(
    const float* __restrict__ ah, const float* __restrict__ W,
    const float* __restrict__ v_att)
{
    __shared__ unsigned int As[128 * AS_STRIDE];
    __shared__ unsigned int Bs[32 * BS_STRIDE];
    __shared__ float su[128];

    const int tid  = threadIdx.x;
    const int warpId = tid >> 5;
    const int lane = tid & 31;
    const int g = lane >> 2;      // groupID
    const int t = lane & 3;       // thread-in-group
    const int warp_m = warpId & 1;   // 2 warps over M (64 rows each)
    const int warp_n = warpId >> 1;  // 4 warps over N (32 cols each)
    const int s0 = blockIdx.x * 128;
    const int h0 = blockIdx.y * 128;
    const int b  = blockIdx.z;

    float acc[4][4][4];
    #pragma unroll
    for (int i = 0; i < 4; i++)
        #pragma unroll
        for (int j = 0; j < 4; j++)
            #pragma unroll
            for (int k = 0; k < 4; k++) acc[i][j][k] = 0.f;

    if (tid < 128) su[tid] = 0.f;

    for (int k0 = 0; k0 < HH; k0 += 32) {
        __syncthreads();
        // A tile: W[h0+m][k0 + 0..31], 128x32 floats = 1024 float4
        #pragma unroll
        for (int i = 0; i < 4; i++) {
            int lin = tid + i * 256;
            int m = lin >> 3, q = lin & 7;
            float4 w4 = *reinterpret_cast<const float4*>(
                &W[(size_t)(h0 + m) * HH + k0 + q * 4]);
            unsigned int* dst = &As[m * AS_STRIDE + q * 4];
            dst[0] = f2tf32(w4.x); dst[1] = f2tf32(w4.y);
            dst[2] = f2tf32(w4.z); dst[3] = f2tf32(w4.w);
        }
        // B tile: ah[b][k0+kk][s0 + 0..127], 32x128 floats = 1024 float4
        #pragma unroll
        for (int i = 0; i < 4; i++) {
            int lin = tid + i * 256;
            int kk = lin >> 5, q = lin & 31;
            float4 x4 = *reinterpret_cast<const float4*>(
                &ah[((size_t)b * HH + k0 + kk) * SS + s0 + q * 4]);
            unsigned int* dst = &Bs[kk * BS_STRIDE + q * 4];
            dst[0] = f2tf32(x4.x); dst[1] = f2tf32(x4.y);
            dst[2] = f2tf32(x4.z); dst[3] = f2tf32(x4.w);
        }
        __syncthreads();

        #pragma unroll
        for (int kk = 0; kk < 32; kk += 8) {
            unsigned int afr[4][4];
            #pragma unroll
            for (int ma = 0; ma < 4; ma++) {
                int r = warp_m * 64 + ma * 16 + g;
                afr[ma][0] = As[r * AS_STRIDE + kk + t];
                afr[ma][1] = As[(r + 8) * AS_STRIDE + kk + t];
                afr[ma][2] = As[r * AS_STRIDE + kk + t + 4];
                afr[ma][3] = As[(r + 8) * AS_STRIDE + kk + t + 4];
            }
            unsigned int bfr[4][2];
            #pragma unroll
            for (int na = 0; na < 4; na++) {
                int c = warp_n * 32 + na * 8 + g;
                bfr[na][0] = Bs[(kk + t) * BS_STRIDE + c];
                bfr[na][1] = Bs[(kk + t + 4) * BS_STRIDE + c];
            }
            #pragma unroll
            for (int ma = 0; ma < 4; ma++)
                #pragma unroll
                for (int na = 0; na < 4; na++) {
                    asm volatile(
                        "mma.sync.aligned.m16n8k8.row.col.f32.tf32.tf32.f32 "
                        "{%0,%1,%2,%3}, {%4,%5,%6,%7}, {%8,%9}, {%0,%1,%2,%3};\n"
                        : "+f"(acc[ma][na][0]), "+f"(acc[ma][na][1]),
                          "+f"(acc[ma][na][2]), "+f"(acc[ma][na][3])
                        : "r"(afr[ma][0]), "r"(afr[ma][1]),
                          "r"(afr[ma][2]), "r"(afr[ma][3]),
                          "r"(bfr[na][0]), "r"(bfr[na][1]));
                }
        }
    }

    // Epilogue: tanh + v_att weighting + per-column reduction.
    // C frag layout: c0:(g,2t) c1:(g,2t+1) c2:(g+8,2t) c3:(g+8,2t+1)
    float vr[4][2];
    #pragma unroll
    for (int ma = 0; ma < 4; ma++) {
        int r = h0 + warp_m * 64 + ma * 16 + g;
        vr[ma][0] = __ldg(&v_att[r]);
        vr[ma][1] = __ldg(&v_att[r + 8]);
    }
    float ucol[8];
    #pragma unroll
    for (int i = 0; i < 8; i++) ucol[i] = 0.f;
    #pragma unroll
    for (int ma = 0; ma < 4; ma++)
        #pragma unroll
        for (int na = 0; na < 4; na++) {
            ucol[na * 2 + 0] += vr[ma][0] * tanhf(acc[ma][na][0])
                              + vr[ma][1] * tanhf(acc[ma][na][2]);
            ucol[na * 2 + 1] += vr[ma][0] * tanhf(acc[ma][na][1])
                              + vr[ma][1] * tanhf(acc[ma][na][3]);
        }
    __syncthreads();
    #pragma unroll
    for (int na = 0; na < 4; na++) {
        atomicAdd(&su[warp_n * 32 + na * 8 + 2 * t + 0], ucol[na * 2 + 0]);
        atomicAdd(&su[warp_n * 32 + na * 8 + 2 * t + 1], ucol[na * 2 + 1]);
    }
    __syncthreads();
    if (tid < 128) g_u_part[blockIdx.y][b][s0 + tid] = su[tid];
}

// ---------------------------------------------------------------------------
// Kernel 2: softmax over s per batch. grid(128), 256 threads, 8 elems/thread.
// ---------------------------------------------------------------------------
__global__ __launch_bounds__(256) void softmax_kernel() {
    const int b = blockIdx.x, tid = threadIdx.x;
    __shared__ float red[8];
    __shared__ float bcast;
    float v[8];
    #pragma unroll
    for (int i = 0; i < 8; i++) {
        int s = tid + i * 256;
        v[i] = g_u_part[0][b][s] + g_u_part[1][b][s]
             + g_u_part[2][b][s] + g_u_part[3][b][s];
    }
    float m = -INFINITY;
    #pragma unroll
    for (int i = 0; i < 8; i++) m = fmaxf(m, v[i]);
    #pragma unroll
    for (int o = 16; o; o >>= 1) m = fmaxf(m, __shfl_xor_sync(0xffffffffu, m, o));
    if ((tid & 31) == 0) red[tid >> 5] = m;
    __syncthreads();
    if (tid == 0) {
        float x = red[0];
        #pragma unroll
        for (int i = 1; i < 8; i++) x = fmaxf(x, red[i]);
        bcast = x;
    }
    __syncthreads();
    m = bcast;
    float sum = 0.f;
    #pragma unroll
    for (int i = 0; i < 8; i++) { v[i] = expf(v[i] - m); sum += v[i]; }
    #pragma unroll
    for (int o = 16; o; o >>= 1) sum += __shfl_xor_sync(0xffffffffu, sum, o);
    __syncthreads();
    if ((tid & 31) == 0) red[tid >> 5] = sum;
    __syncthreads();
    if (tid == 0) {
        float x = 0.f;
        #pragma unroll
        for (int i = 0; i < 8; i++) x += red[i];
        bcast = x;
    }
    __syncthreads();
    float inv = 1.f / bcast;
    #pragma unroll
    for (int i = 0; i < 8; i++) g_attn[b][tid + i * 256] = v[i] * inv;
}

// ---------------------------------------------------------------------------
// Kernel 3: context[b][h] = sum_s attn[b][s] * ah[b][h][s]. One warp per row.
// grid(8192), 256 threads (8 warps).
// ---------------------------------------------------------------------------
__global__ __launch_bounds__(256) void context_kernel(const float* __restrict__ ah) {
    int gw = blockIdx.x * 8 + (threadIdx.x >> 5);
    int lane = threadIdx.x & 31;
    int b = gw >> 9, h = gw & 511;
    const float4* a4 = reinterpret_cast<const float4*>(&ah[((size_t)b * HH + h) * SS]);
    const float4* t4 = reinterpret_cast<const float4*>(&g_attn[b][0]);
    float acc = 0.f;
    #pragma unroll
    for (int it = 0; it < 16; it++) {
        float4 x = a4[it * 32 + lane];
        float4 w = t4[it * 32 + lane];
        acc += x.x * w.x + x.y * w.y + x.z * w.z + x.w * w.w;
    }
    #pragma unroll
    for (int o = 16; o; o >>= 1) acc += __shfl_xor_sync(0xffffffffu, acc, o);
    if (lane == 0) g_context[b][h] = acc;
}

// ---------------------------------------------------------------------------
// Kernel 4: out[b][j] = relu( sum_i in[b][i]*w[j][i] + bias[j] )
// phase 0: g_context -> g_h1 ; phase 1: g_h1 -> g_mlp_out
// grid(128), 512 threads.
// ---------------------------------------------------------------------------
__global__ __launch_bounds__(512) void linear_relu_kernel(
    int phase, const float* __restrict__ w, const float* __restrict__ bias)
{
    __shared__ float s_in[512];
    const int b = blockIdx.x, j = threadIdx.x;
    const float* in = (phase == 0) ? &g_context[0][0] : &g_h1[0][0];
    float* out      = (phase == 0) ? &g_h1[0][0]      : &g_mlp_out[0][0];
    s_in[j] = in[b * 512 + j];
    __syncthreads();
    const float4* w4 = reinterpret_cast<const float4*>(&w[(size_t)j * 512]);
    float acc = bias[j];
    #pragma unroll 8
    for (int i = 0; i < 128; i++) {
        float4 ww = w4[i];
        acc += s_in[4 * i]     * ww.x + s_in[4 * i + 1] * ww.y
             + s_in[4 * i + 2] * ww.z + s_in[4 * i + 3] * ww.w;
    }
    out[b * 512 + j] = fmaxf(acc, 0.f);
}

// ---------------------------------------------------------------------------
// Kernel 5: probs[b][s] = sum_h v_ptr[h] * tanh( ah[b][h][s] + out[b][h] )
// grid(8, 128), 256 threads; each thread owns one s, loops over h.
// ---------------------------------------------------------------------------
__global__ __launch_bounds__(256) void probs_kernel(
    const float* __restrict__ ah, const float* __restrict__ v_ptr,
    float* __restrict__ probs)
{
    __shared__ float s_o[512];
    __shared__ float s_v[512];
    const int tid = threadIdx.x;
    const int b = blockIdx.y;
    const int s = blockIdx.x * 256 + tid;
    s_o[tid] = g_mlp_out[b][tid];
    s_o[tid + 256] = g_mlp_out[b][tid + 256];
    s_v[tid] = v_ptr[tid];
    s_v[tid + 256] = v_ptr[tid + 256];
    __syncthreads();
    const float* base = &ah[(size_t)b * HH * SS + s];
    float acc = 0.f;
    #pragma unroll 8
    for (int h = 0; h < 512; h++) {
        acc += s_v[h] * tanhf(base[(size_t)h * SS] + s_o[h]);
    }
    probs[b * SS + s] = acc;
}

// ---------------------------------------------------------------------------
extern "C" void kernel_launch(void* const* d_in, const int* in_sizes, int n_in,
                              void* d_out, int out_size)
{
    const float* ah    = (const float*)d_in[0];
    const float* v_att = (const float*)d_in[1];
    const float* W_att = (const float*)d_in[2];
    const float* v_ptr = (const float*)d_in[3];
    const float* fc1_w = (const float*)d_in[4];
    const float* fc1_b = (const float*)d_in[5];
    const float* fc2_w = (const float*)d_in[6];
    const float* fc2_b = (const float*)d_in[7];
    float* probs = (float*)d_out;

    dim3 g1(SS / 128, HH / 128, BB);
    scores_u_kernel<<<g1, 256>>>(ah, W_att, v_att);
    softmax_kernel<<<BB, 256>>>();
    context_kernel<<<(BB * HH) / 8, 256>>>(ah);
    linear_relu_kernel<<<BB, 512>>>(0, fc1_w, fc1_b);
    linear_relu_kernel<<<BB, 512>>>(1, fc2_w, fc2_b);
    probs_kernel<<<dim3(SS / 256, BB), 256>>>(ah, v_ptr, probs);
}